// round 15
// baseline (speedup 1.0000x reference)
#include <cuda_runtime.h>
#include <cuda_bf16.h>
#include <cuda_fp16.h>
#include <cstdint>

#define NN 100000
#define EE 260000
#define DD 300
#define D4 75          // DD/4
#define LL 5
#define GG 4096
#define BN_EPS 1e-5f

// ---- HMMA GEMM geometry (fp16 A single-plane, fp16 B hi/lo) ----
#define BM   128
#define BNB  64
#define BKC  64
#define KPAD 320
#define NPAD 320
#define NCHK 5
#define NMAT 13

// smem stage layout (bytes): A | B hi | B lo
#define SA_  0
#define SB_H 16384
#define SB_L 24576
#define STAGE 32768
#define SMEMSZ (2 * STAGE)   // 64 KB dynamic

// ---------------- scratch (device globals; no allocation allowed) ----------
__device__ __align__(16) float  g_h   [(size_t)NN * DD];   // node features (fp32)
__device__ __align__(16) __half g_eh  [(size_t)EE * DD];   // edge features (fp16)
__device__ __align__(16) __half g_tmph[(size_t)EE * DD];   // edge pre-projection (fp16)
__device__ __align__(16) __half g_tmpn[(size_t)NN * DD];   // node fp16 A staging
__device__ __align__(16) float  g_agg [(size_t)NN * DD];
__device__ __align__(16) float  g_out [(size_t)NN * DD];   // mlp2 out (pre-BN)
__device__              float  g_stats[2 * DD];
__device__ __align__(16) float  g_pool[(size_t)GG * DD];
__device__              float  g_cnt [GG];
// preconverted weights: [NMAT][NPAD rows(n)][KPAD cols(k)] fp16, hi and lo planes
__device__ __align__(16) __half g_wfh[(size_t)NMAT * NPAD * KPAD];
__device__ __align__(16) __half g_wfl[(size_t)NMAT * NPAD * KPAD];

// ---------------- helpers ----------------------------------------------------
__device__ __forceinline__ uint32_t smem_u32(const void* p) {
    uint32_t a;
    asm("{ .reg .u64 t; cvta.to.shared.u64 t, %1; cvt.u32.u64 %0, t; }" : "=r"(a) : "l"(p));
    return a;
}
__device__ __forceinline__ uint32_t swz(uint32_t off) { return off ^ ((off >> 3) & 0x70); }

__device__ __forceinline__ void ldsm4(uint32_t* r, uint32_t addr) {
    asm volatile("ldmatrix.sync.aligned.m8n8.x4.shared.b16 {%0,%1,%2,%3}, [%4];"
                 : "=r"(r[0]), "=r"(r[1]), "=r"(r[2]), "=r"(r[3]) : "r"(addr));
}
__device__ __forceinline__ void mma_fp16(float* d, const uint32_t* a, const uint32_t* b) {
    asm("mma.sync.aligned.m16n8k16.row.col.f32.f16.f16.f32 "
        "{%0,%1,%2,%3}, {%4,%5,%6,%7}, {%8,%9}, {%0,%1,%2,%3};"
        : "+f"(d[0]), "+f"(d[1]), "+f"(d[2]), "+f"(d[3])
        : "r"(a[0]), "r"(a[1]), "r"(a[2]), "r"(a[3]), "r"(b[0]), "r"(b[1]));
}
__device__ __forceinline__ void red_add_v4(float* p, float4 v) {
    asm volatile("red.global.add.v4.f32 [%0], {%1, %2, %3, %4};"
                 :: "l"(p), "f"(v.x), "f"(v.y), "f"(v.z), "f"(v.w) : "memory");
}
__device__ __forceinline__ void cp16(uint32_t dst, const void* src) {
    asm volatile("cp.async.ca.shared.global [%0], [%1], 16;" :: "r"(dst), "l"(src));
}
__device__ __forceinline__ void cp8s(uint32_t dst, const void* src, uint32_t ss) {
    asm volatile("cp.async.ca.shared.global [%0], [%1], 8, %2;" :: "r"(dst), "l"(src), "r"(ss));
}
#define CP_COMMIT() asm volatile("cp.async.commit_group;" ::: "memory")
#define CP_WAIT0()  asm volatile("cp.async.wait_group 0;" ::: "memory")

// ---------------- weight preconversion (fp16 hi/lo, [n][k], padded) ----------
__global__ void wprep_k(const float* __restrict__ nap_w2, const float* __restrict__ ee_w2,
                        const float* __restrict__ mlp_w1, const float* __restrict__ mlp_w2,
                        const float* __restrict__ pool_w) {
    int idx = blockIdx.x * blockDim.x + threadIdx.x;
    if (idx >= NMAT * NPAD * KPAD) return;
    int mat = idx / (NPAD * KPAD);
    int rem = idx - mat * (NPAD * KPAD);
    int n = rem / KPAD, k = rem - n * KPAD;
    const float* W;
    if (mat == 0)      W = nap_w2;
    else if (mat == 1) W = ee_w2;
    else if (mat < 7)  W = mlp_w1 + (size_t)(mat - 2) * DD * DD;
    else if (mat < 12) W = mlp_w2 + (size_t)(mat - 7) * DD * DD;
    else               W = pool_w;
    float v = (n < DD && k < DD) ? W[(size_t)k * DD + n] : 0.f;
    __half hi = __float2half_rn(v);
    __half lo = __float2half_rn(v - __half2float(hi));
    g_wfh[idx] = hi;
    g_wfl[idx] = lo;
}

// ---------------- HMMA GEMM --------------------------------------------------
// Block 128x64, warp tile 32x32, fp16 A + fp16 hi/lo B, async fills.
// AM: 0 = A fp32 (LDG->regs, cvt+STS, 2 CTAs/SM), 1 = A fp16 (cp.async, 3 CTAs/SM).
// Epilogue targets (any may be null): C fp32, C2 fp32, Ce fp16.
template<int AM>
__global__ __launch_bounds__(256, AM == 1 ? 3 : 2)
void hgemm_k(const void* __restrict__ Av,
             const __half* __restrict__ Bh, const __half* __restrict__ Bl,
             const float* __restrict__ bias, float* __restrict__ C,
             float* __restrict__ C2, __half* __restrict__ Ce, int M, int relu, int stats,
             const float* __restrict__ gtab, const int* __restrict__ gidx) {
    extern __shared__ char smem[];
    __shared__ float sred[128];
    const uint32_t sb = smem_u32(smem);
    const int tid  = threadIdx.x;
    const int lane = tid & 31;
    const int wid  = tid >> 5;
    const int warpM = wid & 3;
    const int warpN = wid >> 2;
    const int m0 = blockIdx.y * BM;
    const int n0 = blockIdx.x * BNB;

    const int ar   = tid >> 1;
    const int half = tid & 1;
    const int gm_a = m0 + ar;

    float4 pa[8];      // A prefetch regs (AM==0 only)

    auto ldb_async = [&](int c, int s) {
        const uint32_t stb = sb + (s ? STAGE : 0);
        #pragma unroll
        for (int it = 0; it < 2; it++) {
            const int i = tid + it * 256;
            const int n = i >> 3, ku = i & 7;
            const size_t go = (size_t)(n0 + n) * KPAD + c * BKC + ku * 8;
            const uint32_t so = swz(n * 128 + ku * 16);
            cp16(stb + SB_H + so, Bh + go);
            cp16(stb + SB_L + so, Bl + go);
        }
    };
    auto lda_async = [&](int c, int s) {
        const uint32_t stb = sb + (s ? STAGE : 0);
        #pragma unroll
        for (int i = 0; i < 8; i++) {
            const int kl = half * 32 + i * 4;
            const int k  = c * BKC + kl;
            const uint32_t ok = (gm_a < M && k + 4 <= DD) ? 8u : 0u;
            const __half* src = (const __half*)Av
                + (size_t)(ok ? gm_a : 0) * DD + (ok ? k : 0);
            cp8s(stb + SA_ + swz(ar * 128 + kl * 2), src, ok);
        }
    };
    auto lda_regs = [&](int c) {
        #pragma unroll
        for (int i = 0; i < 8; i++) {
            const int kl = half * 32 + i * 4;
            const int k  = c * BKC + kl;
            pa[i] = make_float4(0.f, 0.f, 0.f, 0.f);
            if (gm_a < M && k + 4 <= DD)
                pa[i] = *(const float4*)((const float*)Av + (size_t)gm_a * DD + k);
        }
    };
    auto sts_a = [&](int s) {
        char* st = smem + (s ? STAGE : 0);
        #pragma unroll
        for (int i = 0; i < 8; i++) {
            const int kl = half * 32 + i * 4;
            uint2 u;
            *reinterpret_cast<__half2*>(&u.x) = __floats2half2_rn(pa[i].x, pa[i].y);
            *reinterpret_cast<__half2*>(&u.y) = __floats2half2_rn(pa[i].z, pa[i].w);
            *(uint2*)(st + SA_ + swz(ar * 128 + kl * 2)) = u;
        }
    };

    float acc[2][4][4] = {};

    const int a_row = lane & 15;
    const int a_kc  = (lane >> 4) * 8;
    const int b_row = (lane & 7) + ((lane & 16) ? 8 : 0);
    const int b_kc  = (lane & 8);

    // ---- prologue: fill stage 0
    ldb_async(0, 0);
    if constexpr (AM == 1) lda_async(0, 0);
    CP_COMMIT();
    if constexpr (AM == 0) { lda_regs(0); sts_a(0); }
    CP_WAIT0();
    __syncthreads();

    for (int c = 0; c < NCHK; c++) {
        const int s = c & 1;
        if (c + 1 < NCHK) {
            ldb_async(c + 1, s ^ 1);
            if constexpr (AM == 1) lda_async(c + 1, s ^ 1);
            CP_COMMIT();
            if constexpr (AM == 0) lda_regs(c + 1);
        }

        const uint32_t stb = sb + (s ? STAGE : 0);
        #pragma unroll
        for (int ks = 0; ks < 4; ks++) {
            const int k0 = ks * 16;
            uint32_t ah[2][4], bh[2][4], bl[2][4];
            #pragma unroll
            for (int mt = 0; mt < 2; mt++) {
                const uint32_t off = swz((warpM * 32 + mt * 16 + a_row) * 128 + (k0 + a_kc) * 2);
                ldsm4(ah[mt], stb + SA_ + off);
            }
            #pragma unroll
            for (int g = 0; g < 2; g++) {
                const uint32_t off = swz((warpN * 32 + g * 16 + b_row) * 128 + (k0 + b_kc) * 2);
                ldsm4(bh[g], stb + SB_H + off);
                ldsm4(bl[g], stb + SB_L + off);
            }
            #pragma unroll
            for (int mt = 0; mt < 2; mt++)
                #pragma unroll
                for (int nt = 0; nt < 4; nt++)
                    mma_fp16(acc[mt][nt], ah[mt], &bh[nt >> 1][(nt & 1) * 2]);
            #pragma unroll
            for (int mt = 0; mt < 2; mt++)
                #pragma unroll
                for (int nt = 0; nt < 4; nt++)
                    mma_fp16(acc[mt][nt], ah[mt], &bl[nt >> 1][(nt & 1) * 2]);
        }
        if (c + 1 < NCHK) {
            if constexpr (AM == 0) sts_a(s ^ 1);
            CP_WAIT0();
        }
        __syncthreads();
    }

    // ---- epilogue: bias + optional gather + relu; write C/C2 (fp32), Ce (fp16)
    const int er = lane >> 2;
    const int ec = (lane & 3) * 2;
    float cs[8] = {}, cq[8] = {};
    #pragma unroll
    for (int mt = 0; mt < 2; mt++) {
        #pragma unroll
        for (int rr = 0; rr < 2; rr++) {
            const int gm = m0 + warpM * 32 + mt * 16 + rr * 8 + er;
            if (gm < M) {
                const float* grow = (gtab != nullptr) ? gtab + (size_t)gidx[gm] * DD : nullptr;
                #pragma unroll
                for (int nt = 0; nt < 4; nt++) {
                    const int n = n0 + warpN * 32 + nt * 8 + ec;
                    if (n + 2 <= DD) {
                        float v0 = acc[mt][nt][rr * 2 + 0] + bias[n];
                        float v1 = acc[mt][nt][rr * 2 + 1] + bias[n + 1];
                        if (grow != nullptr) { v0 += grow[n]; v1 += grow[n + 1]; }
                        if (relu) { v0 = fmaxf(v0, 0.f); v1 = fmaxf(v1, 0.f); }
                        if (C != nullptr)
                            *(float2*)&(C + (size_t)gm * DD)[n] = make_float2(v0, v1);
                        if (C2 != nullptr)
                            *(float2*)&(C2 + (size_t)gm * DD)[n] = make_float2(v0, v1);
                        if (Ce != nullptr)
                            *(__half2*)&(Ce + (size_t)gm * DD)[n] = __floats2half2_rn(v0, v1);
                        if (stats) {
                            cs[nt * 2] += v0;     cq[nt * 2] += v0 * v0;
                            cs[nt * 2 + 1] += v1; cq[nt * 2 + 1] += v1 * v1;
                        }
                    }
                }
            }
        }
    }
    if (stats) {
        if (tid < 64) { sred[tid] = 0.f; sred[64 + tid] = 0.f; }
        __syncthreads();
        #pragma unroll
        for (int nt = 0; nt < 4; nt++) {
            const int col = warpN * 32 + nt * 8 + ec;
            atomicAdd(&sred[col],          cs[nt * 2]);
            atomicAdd(&sred[64 + col],     cq[nt * 2]);
            atomicAdd(&sred[col + 1],      cs[nt * 2 + 1]);
            atomicAdd(&sred[64 + col + 1], cq[nt * 2 + 1]);
        }
        __syncthreads();
        if (tid < 64) {
            const int n = n0 + tid;
            if (n < DD) {
                atomicAdd(&g_stats[n],      sred[tid]);
                atomicAdd(&g_stats[DD + n], sred[64 + tid]);
            }
        }
    }
}

// ---------------- elementwise preambles (fp16 outputs) ------------------------
__global__ void node_pre_k(const float* __restrict__ chi, const float* __restrict__ fc,
                           const float* __restrict__ w1, const float* __restrict__ b1) {
    int idx = blockIdx.x * blockDim.x + threadIdx.x;
    if (idx >= NN * D4) return;
    int n = idx / D4, j = idx - n * D4;
    int d = j * 4;
    float c0 = chi[n], c1 = fc[n];
    float4 w0 = *(const float4*)&w1[d];
    float4 w1r = *(const float4*)&w1[DD + d];
    float4 b  = *(const float4*)&b1[d];
    float v0 = fmaxf(c0 * w0.x + c1 * w1r.x + b.x, 0.f);
    float v1 = fmaxf(c0 * w0.y + c1 * w1r.y + b.y, 0.f);
    float v2 = fmaxf(c0 * w0.z + c1 * w1r.z + b.z, 0.f);
    float v3 = fmaxf(c0 * w0.w + c1 * w1r.w + b.w, 0.f);
    uint2 u;
    *reinterpret_cast<__half2*>(&u.x) = __floats2half2_rn(v0, v1);
    *reinterpret_cast<__half2*>(&u.y) = __floats2half2_rn(v2, v3);
    reinterpret_cast<uint2*>(g_tmpn)[idx] = u;
}

__global__ void edge_pre_k(const float* __restrict__ ea,
                           const float* __restrict__ w1, const float* __restrict__ b1) {
    int idx = blockIdx.x * blockDim.x + threadIdx.x;
    if (idx >= EE * D4) return;
    int e = idx / D4, j = idx - e * D4;
    int d = j * 4;
    float c0 = ea[e * 3 + 0], c1 = ea[e * 3 + 1], c2 = ea[e * 3 + 2];
    float4 w0 = *(const float4*)&w1[d];
    float4 w1r = *(const float4*)&w1[DD + d];
    float4 w2r = *(const float4*)&w1[2 * DD + d];
    float4 b  = *(const float4*)&b1[d];
    float v0 = fmaxf(c0 * w0.x + c1 * w1r.x + c2 * w2r.x + b.x, 0.f);
    float v1 = fmaxf(c0 * w0.y + c1 * w1r.y + c2 * w2r.y + b.y, 0.f);
    float v2 = fmaxf(c0 * w0.z + c1 * w1r.z + c2 * w2r.z + b.z, 0.f);
    float v3 = fmaxf(c0 * w0.w + c1 * w1r.w + c2 * w2r.w + b.w, 0.f);
    uint2 u;
    *reinterpret_cast<__half2*>(&u.x) = __floats2half2_rn(v0, v1);
    *reinterpret_cast<__half2*>(&u.y) = __floats2half2_rn(v2, v3);
    reinterpret_cast<uint2*>(g_tmph)[idx] = u;
}

// ---------------- message + scatter-add (fp32 h, fp16 e, vector red) ---------
__global__ void msg_k(const int* __restrict__ ei) {
    int idx = blockIdx.x * blockDim.x + threadIdx.x;
    if (idx >= EE * D4) return;
    int e = idx / D4, j = idx - e * D4;
    int s = __ldg(&ei[e]);
    int d = __ldg(&ei[EE + e]);
    float4 hv = reinterpret_cast<const float4*>(g_h)[(size_t)s * D4 + j];
    uint2 u = *(const uint2*)(g_eh + (size_t)e * DD + j * 4);
    float2 e01 = __half22float2(*reinterpret_cast<__half2*>(&u.x));
    float2 e23 = __half22float2(*reinterpret_cast<__half2*>(&u.y));
    float4 x;
    x.x = fmaxf(hv.x + e01.x, 0.f);
    x.y = fmaxf(hv.y + e01.y, 0.f);
    x.z = fmaxf(hv.z + e23.x, 0.f);
    x.w = fmaxf(hv.w + e23.y, 0.f);
    red_add_v4(&g_agg[(size_t)d * DD + j * 4], x);
}

// ---------------- batchnorm --------------------------------------------------
__global__ void zero_stats_k() {
    int i = threadIdx.x;
    if (i < 2 * DD) g_stats[i] = 0.f;
}

__global__ void bn_apply_k(const float* __restrict__ gamma, const float* __restrict__ beta) {
    int idx = blockIdx.x * blockDim.x + threadIdx.x;
    if (idx >= NN * D4) return;
    int j = idx % D4;
    int d = j * 4;
    const float invN = 1.f / (float)NN;
    float4 mu = make_float4(g_stats[d] * invN, g_stats[d + 1] * invN,
                            g_stats[d + 2] * invN, g_stats[d + 3] * invN);
    float4 ms = make_float4(g_stats[DD + d] * invN, g_stats[DD + d + 1] * invN,
                            g_stats[DD + d + 2] * invN, g_stats[DD + d + 3] * invN);
    float4 ga = *(const float4*)&gamma[d];
    float4 be = *(const float4*)&beta[d];
    float4 o = reinterpret_cast<const float4*>(g_out)[idx];
    float4 v;
    v.x = fmaxf(ga.x * (o.x - mu.x) * rsqrtf(ms.x - mu.x * mu.x + BN_EPS) + be.x, 0.f);
    v.y = fmaxf(ga.y * (o.y - mu.y) * rsqrtf(ms.y - mu.y * mu.y + BN_EPS) + be.y, 0.f);
    v.z = fmaxf(ga.z * (o.z - mu.z) * rsqrtf(ms.z - mu.z * mu.z + BN_EPS) + be.z, 0.f);
    v.w = fmaxf(ga.w * (o.w - mu.w) * rsqrtf(ms.w - mu.w * mu.w + BN_EPS) + be.w, 0.f);
    reinterpret_cast<float4*>(g_h)[idx]   = v;
    reinterpret_cast<float4*>(g_agg)[idx] = v;
}

// ---------------- pooling ----------------------------------------------------
__global__ void pool_zero_k() {
    int idx = blockIdx.x * blockDim.x + threadIdx.x;
    if (idx < GG * DD) g_pool[idx] = 0.f;
    if (idx < GG) g_cnt[idx] = 0.f;
}

__global__ void pool_acc_k(const int* __restrict__ batch) {
    int idx = blockIdx.x * blockDim.x + threadIdx.x;
    if (idx >= NN * D4) return;
    int n = idx / D4, j = idx - n * D4;
    int g = __ldg(&batch[n]);
    float4 v = reinterpret_cast<const float4*>(g_h)[(size_t)n * D4 + j];
    red_add_v4(&g_pool[(size_t)g * DD + j * 4], v);
    if (j == 0) atomicAdd(&g_cnt[g], 1.f);
}

__global__ void pool_div_k() {
    int idx = blockIdx.x * blockDim.x + threadIdx.x;
    if (idx >= GG * D4) return;
    int g = idx / D4, j = idx - g * D4;
    float c = g_cnt[g];
    float inv = (c > 0.f) ? 1.f / c : 0.f;
    float4 v = reinterpret_cast<const float4*>(g_pool)[idx];
    uint2 u;
    *reinterpret_cast<__half2*>(&u.x) = __floats2half2_rn(v.x * inv, v.y * inv);
    *reinterpret_cast<__half2*>(&u.y) = __floats2half2_rn(v.z * inv, v.w * inv);
    reinterpret_cast<uint2*>(g_tmpn)[(size_t)g * D4 + j] = u;
}

// ---------------- launch -----------------------------------------------------
static inline int cdiv(int a, int b) { return (a + b - 1) / b; }

extern "C" void kernel_launch(void* const* d_in, const int* in_sizes, int n_in,
                              void* d_out, int out_size) {
    const int*   z        = (const int*)  d_in[0];
    const float* chi      = (const float*)d_in[1];
    const float* fc       = (const float*)d_in[2];
    const int*   ei       = (const int*)  d_in[3];
    const float* ea       = (const float*)d_in[4];
    const int*   batch    = (const int*)  d_in[5];
    const float* atom_emb = (const float*)d_in[6];
    const float* nap_w1   = (const float*)d_in[7];
    const float* nap_b1   = (const float*)d_in[8];
    const float* nap_w2   = (const float*)d_in[9];
    const float* nap_b2   = (const float*)d_in[10];
    const float* ee_w1    = (const float*)d_in[11];
    const float* ee_b1    = (const float*)d_in[12];
    const float* ee_w2    = (const float*)d_in[13];
    const float* ee_b2    = (const float*)d_in[14];
    const float* mlp_w1   = (const float*)d_in[15];
    const float* mlp_b1   = (const float*)d_in[16];
    const float* mlp_w2   = (const float*)d_in[17];
    const float* mlp_b2   = (const float*)d_in[18];
    const float* bn_gamma = (const float*)d_in[19];
    const float* bn_beta  = (const float*)d_in[20];
    const float* pool_w   = (const float*)d_in[21];
    const float* pool_b   = (const float*)d_in[22];
    float* out = (float*)d_out;

    float *ph, *pagg, *pout, *ppool;
    __half *peh, *ptmph, *ptmpn, *pwh, *pwl;
    cudaGetSymbolAddress((void**)&ph,    g_h);
    cudaGetSymbolAddress((void**)&peh,   g_eh);
    cudaGetSymbolAddress((void**)&ptmph, g_tmph);
    cudaGetSymbolAddress((void**)&ptmpn, g_tmpn);
    cudaGetSymbolAddress((void**)&pagg,  g_agg);
    cudaGetSymbolAddress((void**)&pout,  g_out);
    cudaGetSymbolAddress((void**)&ppool, g_pool);
    cudaGetSymbolAddress((void**)&pwh,   g_wfh);
    cudaGetSymbolAddress((void**)&pwl,   g_wfl);

    cudaFuncSetAttribute(hgemm_k<0>, cudaFuncAttributeMaxDynamicSharedMemorySize, SMEMSZ);
    cudaFuncSetAttribute(hgemm_k<1>, cudaFuncAttributeMaxDynamicSharedMemorySize, SMEMSZ);

    const int TPB = 256;
    const size_t WSTRIDE = (size_t)NPAD * KPAD;
    #define WH(m) (pwh + (size_t)(m) * WSTRIDE)
    #define WL(m) (pwl + (size_t)(m) * WSTRIDE)

    dim3 grid_N(NPAD / BNB, cdiv(NN, BM));
    dim3 grid_E(NPAD / BNB, cdiv(EE, BM));
    dim3 grid_G(NPAD / BNB, cdiv(GG, BM));

    // 0: weight preconversion (fp16 hi/lo)
    wprep_k<<<cdiv(NMAT * NPAD * KPAD, TPB), TPB>>>(nap_w2, ee_w2, mlp_w1, mlp_w2, pool_w);
    // 1: edge pre-projection (fp16 out)
    edge_pre_k<<<cdiv(EE * D4, TPB), TPB>>>(ea, ee_w1, ee_b1);
    // 2: node pre-projection (fp16 out)
    node_pre_k<<<cdiv(NN * D4, TPB), TPB>>>(chi, fc, nap_w1, nap_b1);
    // 3: h0 GEMM (fp16 A): h fp32 + agg fp32
    hgemm_k<1><<<grid_N, 256, SMEMSZ>>>(ptmpn, WH(0), WL(0), nap_b2, ph, pagg, nullptr,
                                        NN, 0, 0, atom_emb, z);
    // 4: edge GEMM (fp16 A, fp16 C)
    hgemm_k<1><<<grid_E, 256, SMEMSZ>>>(ptmph, WH(1), WL(1), ee_b2, nullptr, nullptr, peh,
                                        EE, 0, 0, nullptr, nullptr);

    // ---- L GINE layers
    for (int l = 0; l < LL; l++) {
        msg_k<<<cdiv(EE * D4, TPB), TPB>>>(ei);
        // mlp1: fp32 A (agg), fp16 out (exactly the values mlp2 would quantize anyway)
        hgemm_k<0><<<grid_N, 256, SMEMSZ>>>(pagg, WH(2 + l), WL(2 + l), mlp_b1 + l * DD,
                                            nullptr, nullptr, ptmpn, NN, 1, 0, nullptr, nullptr);
        zero_stats_k<<<1, 2 * DD>>>();
        // mlp2: fp16 A, fp32 out + stats
        hgemm_k<1><<<grid_N, 256, SMEMSZ>>>(ptmpn, WH(7 + l), WL(7 + l), mlp_b2 + l * DD,
                                            pout, nullptr, nullptr, NN, 0, 1, nullptr, nullptr);
        bn_apply_k<<<cdiv(NN * D4, TPB), TPB>>>(bn_gamma + l * DD, bn_beta + l * DD);
    }

    // ---- mean pool per graph + final projection
    pool_zero_k<<<cdiv(GG * DD, TPB), TPB>>>();
    pool_acc_k<<<cdiv(NN * D4, TPB), TPB>>>(batch);
    pool_div_k<<<cdiv(GG * D4, TPB), TPB>>>();
    hgemm_k<1><<<grid_G, 256, SMEMSZ>>>(ptmpn, WH(12), WL(12), pool_b, out, nullptr, nullptr,
                                        GG, 0, 0, nullptr, nullptr);
}

// round 16
// speedup vs baseline: 1.1427x; 1.1427x over previous
#include <cuda_runtime.h>
#include <cuda_bf16.h>
#include <cuda_fp16.h>
#include <cstdint>

#define NN 100000
#define EE 260000
#define DD 300
#define D4 75          // DD/4
#define EDD 304        // fp16 A-plane row stride (16B-aligned rows)
#define LL 5
#define GG 4096
#define BN_EPS 1e-5f

// ---- HMMA GEMM geometry (fp16 A single-plane, fp16 B hi/lo) ----
#define BM   128
#define BNB  64
#define BKC  64
#define KPAD 320
#define NPAD 320
#define NCHK 5
#define NMAT 13

// smem stage layout (bytes): A | B hi | B lo
#define SA_  0
#define SB_H 16384
#define SB_L 24576
#define STAGE 32768
#define SMEMSZ (2 * STAGE)   // 64 KB dynamic -> 2 CTAs/SM

// ---------------- scratch (device globals; no allocation allowed) ----------
__device__ __align__(16) float  g_h   [(size_t)NN * DD];    // node features (fp32)
__device__ __align__(16) __half g_eh  [(size_t)EE * EDD];   // edge features (fp16, stride 304)
__device__ __align__(16) __half g_tmph[(size_t)EE * EDD];   // edge pre-projection (fp16)
__device__ __align__(16) __half g_tmpn[(size_t)NN * EDD];   // node fp16 A staging
__device__ __align__(16) float  g_agg [(size_t)NN * DD];
__device__ __align__(16) float  g_out [(size_t)NN * DD];    // mlp2 out (pre-BN)
__device__              float  g_stats[2 * DD];
__device__ __align__(16) float  g_pool[(size_t)GG * DD];
__device__              float  g_cnt [GG];
// preconverted weights: [NMAT][NPAD rows(n)][KPAD cols(k)] fp16, hi and lo planes
__device__ __align__(16) __half g_wfh[(size_t)NMAT * NPAD * KPAD];
__device__ __align__(16) __half g_wfl[(size_t)NMAT * NPAD * KPAD];

// ---------------- helpers ----------------------------------------------------
__device__ __forceinline__ uint32_t smem_u32(const void* p) {
    uint32_t a;
    asm("{ .reg .u64 t; cvta.to.shared.u64 t, %1; cvt.u32.u64 %0, t; }" : "=r"(a) : "l"(p));
    return a;
}
__device__ __forceinline__ uint32_t swz(uint32_t off) { return off ^ ((off >> 3) & 0x70); }

__device__ __forceinline__ void ldsm4(uint32_t* r, uint32_t addr) {
    asm volatile("ldmatrix.sync.aligned.m8n8.x4.shared.b16 {%0,%1,%2,%3}, [%4];"
                 : "=r"(r[0]), "=r"(r[1]), "=r"(r[2]), "=r"(r[3]) : "r"(addr));
}
__device__ __forceinline__ void mma_fp16(float* d, const uint32_t* a, const uint32_t* b) {
    asm("mma.sync.aligned.m16n8k16.row.col.f32.f16.f16.f32 "
        "{%0,%1,%2,%3}, {%4,%5,%6,%7}, {%8,%9}, {%0,%1,%2,%3};"
        : "+f"(d[0]), "+f"(d[1]), "+f"(d[2]), "+f"(d[3])
        : "r"(a[0]), "r"(a[1]), "r"(a[2]), "r"(a[3]), "r"(b[0]), "r"(b[1]));
}
__device__ __forceinline__ void red_add_v4(float* p, float4 v) {
    asm volatile("red.global.add.v4.f32 [%0], {%1, %2, %3, %4};"
                 :: "l"(p), "f"(v.x), "f"(v.y), "f"(v.z), "f"(v.w) : "memory");
}
__device__ __forceinline__ void cp16(uint32_t dst, const void* src) {
    asm volatile("cp.async.ca.shared.global [%0], [%1], 16;" :: "r"(dst), "l"(src));
}
#define CP_COMMIT() asm volatile("cp.async.commit_group;" ::: "memory")
#define CP_WAIT0()  asm volatile("cp.async.wait_group 0;" ::: "memory")

// ---------------- weight preconversion (fp16 hi/lo, [n][k], padded) ----------
__global__ void wprep_k(const float* __restrict__ nap_w2, const float* __restrict__ ee_w2,
                        const float* __restrict__ mlp_w1, const float* __restrict__ mlp_w2,
                        const float* __restrict__ pool_w) {
    int idx = blockIdx.x * blockDim.x + threadIdx.x;
    if (idx >= NMAT * NPAD * KPAD) return;
    int mat = idx / (NPAD * KPAD);
    int rem = idx - mat * (NPAD * KPAD);
    int n = rem / KPAD, k = rem - n * KPAD;
    const float* W;
    if (mat == 0)      W = nap_w2;
    else if (mat == 1) W = ee_w2;
    else if (mat < 7)  W = mlp_w1 + (size_t)(mat - 2) * DD * DD;
    else if (mat < 12) W = mlp_w2 + (size_t)(mat - 7) * DD * DD;
    else               W = pool_w;
    float v = (n < DD && k < DD) ? W[(size_t)k * DD + n] : 0.f;
    __half hi = __float2half_rn(v);
    __half lo = __float2half_rn(v - __half2float(hi));
    g_wfh[idx] = hi;
    g_wfl[idx] = lo;
}

// ---------------- HMMA GEMM --------------------------------------------------
// Block 128x64, warp tile 32x32, fp16 A + fp16 hi/lo B, B via cp.async.
// AM=0: A fp32 stride DD  (8x LDG.128 + 8x STS.64 per thread per chunk)
// AM=2: A fp16 stride EDD (4x LDG.128 + 4x STS.128 per thread per chunk) — half fill ops.
// Epilogue targets (any may be null): C fp32 (DD), C2 fp32 (DD), Ce fp16 (EDD).
template<int AM>
__global__ __launch_bounds__(256, 2)
void hgemm_k(const void* __restrict__ Av,
             const __half* __restrict__ Bh, const __half* __restrict__ Bl,
             const float* __restrict__ bias, float* __restrict__ C,
             float* __restrict__ C2, __half* __restrict__ Ce, int M, int relu, int stats,
             const float* __restrict__ gtab, const int* __restrict__ gidx) {
    extern __shared__ char smem[];
    __shared__ float sred[128];
    const uint32_t sb = smem_u32(smem);
    const int tid  = threadIdx.x;
    const int lane = tid & 31;
    const int wid  = tid >> 5;
    const int warpM = wid & 3;
    const int warpN = wid >> 2;
    const int m0 = blockIdx.y * BM;
    const int n0 = blockIdx.x * BNB;

    const int ar   = tid >> 1;
    const int half = tid & 1;
    const int gm_a = m0 + ar;

    float4 pa[8];      // AM==0 prefetch regs
    uint4  pa16[4];    // AM==2 prefetch regs

    auto ldb_async = [&](int c, int s) {
        const uint32_t stb = sb + (s ? STAGE : 0);
        #pragma unroll
        for (int it = 0; it < 2; it++) {
            const int i = tid + it * 256;
            const int n = i >> 3, ku = i & 7;
            const size_t go = (size_t)(n0 + n) * KPAD + c * BKC + ku * 8;
            const uint32_t so = swz(n * 128 + ku * 16);
            cp16(stb + SB_H + so, Bh + go);
            cp16(stb + SB_L + so, Bl + go);
        }
    };
    auto lda_regs = [&](int c) {
        if constexpr (AM == 0) {
            #pragma unroll
            for (int i = 0; i < 8; i++) {
                const int kl = half * 32 + i * 4;
                const int k  = c * BKC + kl;
                pa[i] = make_float4(0.f, 0.f, 0.f, 0.f);
                if (gm_a < M && k + 4 <= DD)
                    pa[i] = *(const float4*)((const float*)Av + (size_t)gm_a * DD + k);
            }
        } else {
            #pragma unroll
            for (int i = 0; i < 4; i++) {
                const int kl = half * 32 + i * 8;
                const int k  = c * BKC + kl;
                pa16[i] = make_uint4(0u, 0u, 0u, 0u);
                // k=296 vector covers 296..303 (garbage in 300..303 is annihilated
                // by zero-padded B); k>=304 is outside the padded row -> zero.
                if (gm_a < M && k < EDD)
                    pa16[i] = *(const uint4*)((const __half*)Av + (size_t)gm_a * EDD + k);
            }
        }
    };
    auto sts_a = [&](int s) {
        char* st = smem + (s ? STAGE : 0);
        if constexpr (AM == 0) {
            #pragma unroll
            for (int i = 0; i < 8; i++) {
                const int kl = half * 32 + i * 4;
                uint2 u;
                *reinterpret_cast<__half2*>(&u.x) = __floats2half2_rn(pa[i].x, pa[i].y);
                *reinterpret_cast<__half2*>(&u.y) = __floats2half2_rn(pa[i].z, pa[i].w);
                *(uint2*)(st + SA_ + swz(ar * 128 + kl * 2)) = u;
            }
        } else {
            #pragma unroll
            for (int i = 0; i < 4; i++) {
                const int kl = half * 32 + i * 8;
                *(uint4*)(st + SA_ + swz(ar * 128 + kl * 2)) = pa16[i];
            }
        }
    };

    float acc[2][4][4] = {};

    const int a_row = lane & 15;
    const int a_kc  = (lane >> 4) * 8;
    const int b_row = (lane & 7) + ((lane & 16) ? 8 : 0);
    const int b_kc  = (lane & 8);

    // ---- prologue: fill stage 0
    ldb_async(0, 0);
    CP_COMMIT();
    lda_regs(0);
    sts_a(0);
    CP_WAIT0();
    __syncthreads();

    for (int c = 0; c < NCHK; c++) {
        const int s = c & 1;
        if (c + 1 < NCHK) {
            ldb_async(c + 1, s ^ 1);
            CP_COMMIT();
            lda_regs(c + 1);
        }

        const uint32_t stb = sb + (s ? STAGE : 0);
        #pragma unroll
        for (int ks = 0; ks < 4; ks++) {
            const int k0 = ks * 16;
            uint32_t ah[2][4], bh[2][4], bl[2][4];
            #pragma unroll
            for (int mt = 0; mt < 2; mt++) {
                const uint32_t off = swz((warpM * 32 + mt * 16 + a_row) * 128 + (k0 + a_kc) * 2);
                ldsm4(ah[mt], stb + SA_ + off);
            }
            #pragma unroll
            for (int g = 0; g < 2; g++) {
                const uint32_t off = swz((warpN * 32 + g * 16 + b_row) * 128 + (k0 + b_kc) * 2);
                ldsm4(bh[g], stb + SB_H + off);
                ldsm4(bl[g], stb + SB_L + off);
            }
            #pragma unroll
            for (int mt = 0; mt < 2; mt++)
                #pragma unroll
                for (int nt = 0; nt < 4; nt++)
                    mma_fp16(acc[mt][nt], ah[mt], &bh[nt >> 1][(nt & 1) * 2]);
            #pragma unroll
            for (int mt = 0; mt < 2; mt++)
                #pragma unroll
                for (int nt = 0; nt < 4; nt++)
                    mma_fp16(acc[mt][nt], ah[mt], &bl[nt >> 1][(nt & 1) * 2]);
        }
        if (c + 1 < NCHK) {
            sts_a(s ^ 1);
            CP_WAIT0();
        }
        __syncthreads();
    }

    // ---- epilogue: bias + optional gather + relu; write C/C2 (fp32), Ce (fp16)
    const int er = lane >> 2;
    const int ec = (lane & 3) * 2;
    float cs[8] = {}, cq[8] = {};
    #pragma unroll
    for (int mt = 0; mt < 2; mt++) {
        #pragma unroll
        for (int rr = 0; rr < 2; rr++) {
            const int gm = m0 + warpM * 32 + mt * 16 + rr * 8 + er;
            if (gm < M) {
                const float* grow = (gtab != nullptr) ? gtab + (size_t)gidx[gm] * DD : nullptr;
                #pragma unroll
                for (int nt = 0; nt < 4; nt++) {
                    const int n = n0 + warpN * 32 + nt * 8 + ec;
                    if (n + 2 <= DD) {
                        float v0 = acc[mt][nt][rr * 2 + 0] + bias[n];
                        float v1 = acc[mt][nt][rr * 2 + 1] + bias[n + 1];
                        if (grow != nullptr) { v0 += grow[n]; v1 += grow[n + 1]; }
                        if (relu) { v0 = fmaxf(v0, 0.f); v1 = fmaxf(v1, 0.f); }
                        if (C != nullptr)
                            *(float2*)&(C + (size_t)gm * DD)[n] = make_float2(v0, v1);
                        if (C2 != nullptr)
                            *(float2*)&(C2 + (size_t)gm * DD)[n] = make_float2(v0, v1);
                        if (Ce != nullptr)
                            *(__half2*)&(Ce + (size_t)gm * EDD)[n] = __floats2half2_rn(v0, v1);
                        if (stats) {
                            cs[nt * 2] += v0;     cq[nt * 2] += v0 * v0;
                            cs[nt * 2 + 1] += v1; cq[nt * 2 + 1] += v1 * v1;
                        }
                    }
                }
            }
        }
    }
    if (stats) {
        if (tid < 64) { sred[tid] = 0.f; sred[64 + tid] = 0.f; }
        __syncthreads();
        #pragma unroll
        for (int nt = 0; nt < 4; nt++) {
            const int col = warpN * 32 + nt * 8 + ec;
            atomicAdd(&sred[col],          cs[nt * 2]);
            atomicAdd(&sred[64 + col],     cq[nt * 2]);
            atomicAdd(&sred[col + 1],      cs[nt * 2 + 1]);
            atomicAdd(&sred[64 + col + 1], cq[nt * 2 + 1]);
        }
        __syncthreads();
        if (tid < 64) {
            const int n = n0 + tid;
            if (n < DD) {
                atomicAdd(&g_stats[n],      sred[tid]);
                atomicAdd(&g_stats[DD + n], sred[64 + tid]);
            }
        }
    }
}

// ---------------- elementwise preambles (fp16 out, stride EDD) ---------------
__global__ void node_pre_k(const float* __restrict__ chi, const float* __restrict__ fc,
                           const float* __restrict__ w1, const float* __restrict__ b1) {
    int idx = blockIdx.x * blockDim.x + threadIdx.x;
    if (idx >= NN * D4) return;
    int n = idx / D4, j = idx - n * D4;
    int d = j * 4;
    float c0 = chi[n], c1 = fc[n];
    float4 w0 = *(const float4*)&w1[d];
    float4 w1r = *(const float4*)&w1[DD + d];
    float4 b  = *(const float4*)&b1[d];
    float v0 = fmaxf(c0 * w0.x + c1 * w1r.x + b.x, 0.f);
    float v1 = fmaxf(c0 * w0.y + c1 * w1r.y + b.y, 0.f);
    float v2 = fmaxf(c0 * w0.z + c1 * w1r.z + b.z, 0.f);
    float v3 = fmaxf(c0 * w0.w + c1 * w1r.w + b.w, 0.f);
    uint2 u;
    *reinterpret_cast<__half2*>(&u.x) = __floats2half2_rn(v0, v1);
    *reinterpret_cast<__half2*>(&u.y) = __floats2half2_rn(v2, v3);
    *(uint2*)(g_tmpn + (size_t)n * EDD + d) = u;
}

__global__ void edge_pre_k(const float* __restrict__ ea,
                           const float* __restrict__ w1, const float* __restrict__ b1) {
    int idx = blockIdx.x * blockDim.x + threadIdx.x;
    if (idx >= EE * D4) return;
    int e = idx / D4, j = idx - e * D4;
    int d = j * 4;
    float c0 = ea[e * 3 + 0], c1 = ea[e * 3 + 1], c2 = ea[e * 3 + 2];
    float4 w0 = *(const float4*)&w1[d];
    float4 w1r = *(const float4*)&w1[DD + d];
    float4 w2r = *(const float4*)&w1[2 * DD + d];
    float4 b  = *(const float4*)&b1[d];
    float v0 = fmaxf(c0 * w0.x + c1 * w1r.x + c2 * w2r.x + b.x, 0.f);
    float v1 = fmaxf(c0 * w0.y + c1 * w1r.y + c2 * w2r.y + b.y, 0.f);
    float v2 = fmaxf(c0 * w0.z + c1 * w1r.z + c2 * w2r.z + b.z, 0.f);
    float v3 = fmaxf(c0 * w0.w + c1 * w1r.w + c2 * w2r.w + b.w, 0.f);
    uint2 u;
    *reinterpret_cast<__half2*>(&u.x) = __floats2half2_rn(v0, v1);
    *reinterpret_cast<__half2*>(&u.y) = __floats2half2_rn(v2, v3);
    *(uint2*)(g_tmph + (size_t)e * EDD + d) = u;
}

// ---------------- message + scatter-add (fp32 h, fp16 e, vector red) ---------
__global__ void msg_k(const int* __restrict__ ei) {
    int idx = blockIdx.x * blockDim.x + threadIdx.x;
    if (idx >= EE * D4) return;
    int e = idx / D4, j = idx - e * D4;
    int s = __ldg(&ei[e]);
    int d = __ldg(&ei[EE + e]);
    float4 hv = reinterpret_cast<const float4*>(g_h)[(size_t)s * D4 + j];
    uint2 u = *(const uint2*)(g_eh + (size_t)e * EDD + j * 4);
    float2 e01 = __half22float2(*reinterpret_cast<__half2*>(&u.x));
    float2 e23 = __half22float2(*reinterpret_cast<__half2*>(&u.y));
    float4 x;
    x.x = fmaxf(hv.x + e01.x, 0.f);
    x.y = fmaxf(hv.y + e01.y, 0.f);
    x.z = fmaxf(hv.z + e23.x, 0.f);
    x.w = fmaxf(hv.w + e23.y, 0.f);
    red_add_v4(&g_agg[(size_t)d * DD + j * 4], x);
}

// ---------------- batchnorm --------------------------------------------------
__global__ void zero_stats_k() {
    int i = threadIdx.x;
    if (i < 2 * DD) g_stats[i] = 0.f;
}

__global__ void bn_apply_k(const float* __restrict__ gamma, const float* __restrict__ beta) {
    int idx = blockIdx.x * blockDim.x + threadIdx.x;
    if (idx >= NN * D4) return;
    int j = idx % D4;
    int d = j * 4;
    const float invN = 1.f / (float)NN;
    float4 mu = make_float4(g_stats[d] * invN, g_stats[d + 1] * invN,
                            g_stats[d + 2] * invN, g_stats[d + 3] * invN);
    float4 ms = make_float4(g_stats[DD + d] * invN, g_stats[DD + d + 1] * invN,
                            g_stats[DD + d + 2] * invN, g_stats[DD + d + 3] * invN);
    float4 ga = *(const float4*)&gamma[d];
    float4 be = *(const float4*)&beta[d];
    float4 o = reinterpret_cast<const float4*>(g_out)[idx];
    float4 v;
    v.x = fmaxf(ga.x * (o.x - mu.x) * rsqrtf(ms.x - mu.x * mu.x + BN_EPS) + be.x, 0.f);
    v.y = fmaxf(ga.y * (o.y - mu.y) * rsqrtf(ms.y - mu.y * mu.y + BN_EPS) + be.y, 0.f);
    v.z = fmaxf(ga.z * (o.z - mu.z) * rsqrtf(ms.z - mu.z * mu.z + BN_EPS) + be.z, 0.f);
    v.w = fmaxf(ga.w * (o.w - mu.w) * rsqrtf(ms.w - mu.w * mu.w + BN_EPS) + be.w, 0.f);
    reinterpret_cast<float4*>(g_h)[idx]   = v;
    reinterpret_cast<float4*>(g_agg)[idx] = v;
}

// ---------------- pooling ----------------------------------------------------
__global__ void pool_zero_k() {
    int idx = blockIdx.x * blockDim.x + threadIdx.x;
    if (idx < GG * DD) g_pool[idx] = 0.f;
    if (idx < GG) g_cnt[idx] = 0.f;
}

__global__ void pool_acc_k(const int* __restrict__ batch) {
    int idx = blockIdx.x * blockDim.x + threadIdx.x;
    if (idx >= NN * D4) return;
    int n = idx / D4, j = idx - n * D4;
    int g = __ldg(&batch[n]);
    float4 v = reinterpret_cast<const float4*>(g_h)[(size_t)n * D4 + j];
    red_add_v4(&g_pool[(size_t)g * DD + j * 4], v);
    if (j == 0) atomicAdd(&g_cnt[g], 1.f);
}

__global__ void pool_div_k() {
    int idx = blockIdx.x * blockDim.x + threadIdx.x;
    if (idx >= GG * D4) return;
    int g = idx / D4, j = idx - g * D4;
    float c = g_cnt[g];
    float inv = (c > 0.f) ? 1.f / c : 0.f;
    float4 v = reinterpret_cast<const float4*>(g_pool)[idx];
    uint2 u;
    *reinterpret_cast<__half2*>(&u.x) = __floats2half2_rn(v.x * inv, v.y * inv);
    *reinterpret_cast<__half2*>(&u.y) = __floats2half2_rn(v.z * inv, v.w * inv);
    *(uint2*)(g_tmpn + (size_t)g * EDD + j * 4) = u;
}

// ---------------- launch -----------------------------------------------------
static inline int cdiv(int a, int b) { return (a + b - 1) / b; }

extern "C" void kernel_launch(void* const* d_in, const int* in_sizes, int n_in,
                              void* d_out, int out_size) {
    const int*   z        = (const int*)  d_in[0];
    const float* chi      = (const float*)d_in[1];
    const float* fc       = (const float*)d_in[2];
    const int*   ei       = (const int*)  d_in[3];
    const float* ea       = (const float*)d_in[4];
    const int*   batch    = (const int*)  d_in[5];
    const float* atom_emb = (const float*)d_in[6];
    const float* nap_w1   = (const float*)d_in[7];
    const float* nap_b1   = (const float*)d_in[8];
    const float* nap_w2   = (const float*)d_in[9];
    const float* nap_b2   = (const float*)d_in[10];
    const float* ee_w1    = (const float*)d_in[11];
    const float* ee_b1    = (const float*)d_in[12];
    const float* ee_w2    = (const float*)d_in[13];
    const float* ee_b2    = (const float*)d_in[14];
    const float* mlp_w1   = (const float*)d_in[15];
    const float* mlp_b1   = (const float*)d_in[16];
    const float* mlp_w2   = (const float*)d_in[17];
    const float* mlp_b2   = (const float*)d_in[18];
    const float* bn_gamma = (const float*)d_in[19];
    const float* bn_beta  = (const float*)d_in[20];
    const float* pool_w   = (const float*)d_in[21];
    const float* pool_b   = (const float*)d_in[22];
    float* out = (float*)d_out;

    float *ph, *pagg, *pout, *ppool;
    __half *peh, *ptmph, *ptmpn, *pwh, *pwl;
    cudaGetSymbolAddress((void**)&ph,    g_h);
    cudaGetSymbolAddress((void**)&peh,   g_eh);
    cudaGetSymbolAddress((void**)&ptmph, g_tmph);
    cudaGetSymbolAddress((void**)&ptmpn, g_tmpn);
    cudaGetSymbolAddress((void**)&pagg,  g_agg);
    cudaGetSymbolAddress((void**)&pout,  g_out);
    cudaGetSymbolAddress((void**)&ppool, g_pool);
    cudaGetSymbolAddress((void**)&pwh,   g_wfh);
    cudaGetSymbolAddress((void**)&pwl,   g_wfl);

    cudaFuncSetAttribute(hgemm_k<0>, cudaFuncAttributeMaxDynamicSharedMemorySize, SMEMSZ);
    cudaFuncSetAttribute(hgemm_k<2>, cudaFuncAttributeMaxDynamicSharedMemorySize, SMEMSZ);

    const int TPB = 256;
    const size_t WSTRIDE = (size_t)NPAD * KPAD;
    #define WH(m) (pwh + (size_t)(m) * WSTRIDE)
    #define WL(m) (pwl + (size_t)(m) * WSTRIDE)

    dim3 grid_N(NPAD / BNB, cdiv(NN, BM));
    dim3 grid_E(NPAD / BNB, cdiv(EE, BM));
    dim3 grid_G(NPAD / BNB, cdiv(GG, BM));

    // 0: weight preconversion (fp16 hi/lo)
    wprep_k<<<cdiv(NMAT * NPAD * KPAD, TPB), TPB>>>(nap_w2, ee_w2, mlp_w1, mlp_w2, pool_w);
    // 1: edge pre-projection (fp16 out)
    edge_pre_k<<<cdiv(EE * D4, TPB), TPB>>>(ea, ee_w1, ee_b1);
    // 2: node pre-projection (fp16 out)
    node_pre_k<<<cdiv(NN * D4, TPB), TPB>>>(chi, fc, nap_w1, nap_b1);
    // 3: h0 GEMM (fp16 A): h fp32 + agg fp32 (profiled slot)
    hgemm_k<2><<<grid_N, 256, SMEMSZ>>>(ptmpn, WH(0), WL(0), nap_b2, ph, pagg, nullptr,
                                        NN, 0, 0, atom_emb, z);
    // 4: edge GEMM (fp16 A, fp16 C)
    hgemm_k<2><<<grid_E, 256, SMEMSZ>>>(ptmph, WH(1), WL(1), ee_b2, nullptr, nullptr, peh,
                                        EE, 0, 0, nullptr, nullptr);

    // ---- L GINE layers
    for (int l = 0; l < LL; l++) {
        msg_k<<<cdiv(EE * D4, TPB), TPB>>>(ei);
        // mlp1: fp32 A (agg), fp16 out (identical to in-GEMM quantization)
        hgemm_k<0><<<grid_N, 256, SMEMSZ>>>(pagg, WH(2 + l), WL(2 + l), mlp_b1 + l * DD,
                                            nullptr, nullptr, ptmpn, NN, 1, 0, nullptr, nullptr);
        zero_stats_k<<<1, 2 * DD>>>();
        // mlp2: fp16 A, fp32 out + stats
        hgemm_k<2><<<grid_N, 256, SMEMSZ>>>(ptmpn, WH(7 + l), WL(7 + l), mlp_b2 + l * DD,
                                            pout, nullptr, nullptr, NN, 0, 1, nullptr, nullptr);
        bn_apply_k<<<cdiv(NN * D4, TPB), TPB>>>(bn_gamma + l * DD, bn_beta + l * DD);
    }

    // ---- mean pool per graph + final projection
    pool_zero_k<<<cdiv(GG * DD, TPB), TPB>>>();
    pool_acc_k<<<cdiv(NN * D4, TPB), TPB>>>(batch);
    pool_div_k<<<cdiv(GG * D4, TPB), TPB>>>();
    hgemm_k<2><<<grid_G, 256, SMEMSZ>>>(ptmpn, WH(12), WL(12), pool_b, out, nullptr, nullptr,
                                        GG, 0, 0, nullptr, nullptr);
}